// round 16
// baseline (speedup 1.0000x reference)
#include <cuda_runtime.h>
#include <cub/cub.cuh>
#include <cstdint>

#define NIMG 8
#define ATOT 65472
#define KC 6960
#define NSEG 40
#define SEGCAP 2048
#define SELCAP 4096
#define POST 2000
#define AMB_CAP 65536
#define NBIN 4096

// ---------------- static device scratch (no runtime allocation) ----------------
__device__ float4             g_cbox[NSEG*SEGCAP];       // clipped boxes, (seg,rank)
__device__ float              g_score[NSEG*SEGCAP];
__device__ unsigned           g_segmax[NSEG];            // float bits of per-seg coord max
__device__ unsigned long long g_seginval[NSEG*32];
__device__ unsigned long long g_mask[(size_t)NSEG*SEGCAP*32];  // ~21 MB suppression bitmask
__device__ unsigned long long g_ckeys[NSEG*SEGCAP];     // per-seg compact kept keys (asc)
__device__ unsigned           g_segcnt[NSEG];
__device__ unsigned           g_ambcnt;
__device__ unsigned           g_amb[AMB_CAP];

typedef cub::BlockRadixSort<unsigned long long, 1024, 4, cub::NullType, 6> SelSortT;

// ---------------- helpers ----------------
__device__ __forceinline__ int lvl_of_p(int p){
    return (p<2000)?0:(p<4000)?1:(p<6000)?2:(p<6768)?3:4;
}
__device__ __forceinline__ int loff_of(int l){
    return (l==0)?0:(l==1)?49152:(l==2)?61440:(l==3)?64512:65280;
}
__device__ __forceinline__ int nlvl_of(int l){
    return (l==0)?49152:(l==1)?12288:(l==2)?3072:(l==3)?768:192;
}
__device__ __forceinline__ int coff_of(int l){
    return (l==0)?0:(l==1)?2000:(l==2)?4000:(l==3)?6000:6768;
}
__device__ __forceinline__ int segk_of(int l){
    return (l<3)?2000:(l==3)?768:192;
}
__device__ __forceinline__ unsigned fordera(float f){
    unsigned b = __float_as_uint(f);
    return (b & 0x80000000u) ? ~b : (b | 0x80000000u);
}
// image coordinate max from per-segment maxes (exact max, order-free)
__device__ __forceinline__ float img_mp1(int i){
    float mx =            __uint_as_float(g_segmax[i*5+0]);
    mx = fmaxf(mx, __uint_as_float(g_segmax[i*5+1]));
    mx = fmaxf(mx, __uint_as_float(g_segmax[i*5+2]));
    mx = fmaxf(mx, __uint_as_float(g_segmax[i*5+3]));
    mx = fmaxf(mx, __uint_as_float(g_segmax[i*5+4]));
    return __fadd_rn(mx, 1.0f);
}

// XLA logistic: 0.5 + 0.5*tanh(0.5x), tanh = EmitFastTanh rational (Eigen coeffs).
__device__ __forceinline__ float sigmoid_ref(float x){
    float t  = __fmul_rn(0.5f, x);
    float r;
    if (fabsf(t) < 0.0004f) {
        r = t;
    } else {
        float tc = fmaxf(-9.0f, fminf(9.0f, t));
        float s  = __fmul_rn(tc, tc);
        float p  = __fmaf_rn(s, -2.76076847742355e-16f, 2.00018790482477e-13f);
        p = __fmaf_rn(p, s, -8.60467152213735e-11f);
        p = __fmaf_rn(p, s,  5.12229709037114e-08f);
        p = __fmaf_rn(p, s,  1.48572235717979e-05f);
        p = __fmaf_rn(p, s,  6.37261928875436e-04f);
        p = __fmaf_rn(p, s,  4.89352455891786e-03f);
        p = __fmul_rn(p, tc);
        float q = __fmaf_rn(s, 1.19825839466702e-06f, 1.18534705686654e-04f);
        q = __fmaf_rn(q, s, 2.26843463243900e-03f);
        q = __fmaf_rn(q, s, 4.89352518554385e-03f);
        r = __fdiv_rn(p, q);
    }
    return __fmaf_rn(0.5f, r, 0.5f);
}

// Exact predicate: RN(a/u) > 0.7f  <=>  a/u >= m,  m = 0.7f + 2^-25 = 23488103*2^-25.
__device__ __forceinline__ bool exact_pred(float a, float u){
    if (!(a > 0.f) || !(u > 0.f)) return false;
    unsigned ia = __float_as_uint(a), iu = __float_as_uint(u);
    int d = (int)(ia >> 23) - (int)(iu >> 23);
    if (d > 0)  return true;
    if (d < -1) return false;
    unsigned long long Ma = (ia & 0x7FFFFFu) | 0x800000u;
    unsigned long long Mu = (iu & 0x7FFFFFu) | 0x800000u;
    return (Ma << (d + 25)) >= 23488103ull * Mu;
}

// ---------------- kernels ----------------
// Fused per-segment: histogram threshold select + atomic compaction (48-bit
// composite key canonicalizes order) + in-block sort + candidate build.
__global__ void __launch_bounds__(1024) k_sel2(const float* __restrict__ obj,
                                               const float* __restrict__ props){
    int seg = blockIdx.x, i = seg/5, l = seg%5;
    int n = nlvl_of(l), kk = segk_of(l);
    int t = threadIdx.x;
    extern __shared__ unsigned char dsm[];
    unsigned* hist = (unsigned*)dsm;                          // 16KB
    unsigned long long* skey = (unsigned long long*)dsm;      // 32KB (aliases hist)
    auto* sortTS = reinterpret_cast<SelSortT::TempStorage*>(dsm + 32768);
    typedef cub::BlockScan<int, 1024> BS;
    __shared__ typename BS::TempStorage ts;
    __shared__ int sB;
    __shared__ unsigned sCnt, sMax;

    if (seg == 0 && t == 0) g_ambcnt = 0u;
    if (t == 0){ sCnt = 0u; sMax = 0u; }
    if (t < 32){                                     // padding ranks start invalid
        int r0 = t*64;
        unsigned long long v = (kk <= r0) ? ~0ull :
                               (kk >= r0+64) ? 0ull : (~0ull << (kk - r0));
        g_seginval[seg*32 + t] = v;
    }
    for (int b = t; b < NBIN; b += 1024) hist[b] = 0u;
    __syncthreads();

    const float* base = obj + (size_t)i*ATOT + loff_of(l);
    for (int s = t; s < n; s += 1024){
        unsigned d = ~fordera(base[s]);
        atomicAdd(&hist[d >> 20], 1u);
    }
    __syncthreads();

    {   // threshold bucket: first bucket where cumulative >= kk
        int b0 = t*4, s4 = 0;
#pragma unroll
        for (int j = 0; j < 4; j++) s4 += (int)hist[b0 + j];
        int ex;
        BS(ts).ExclusiveSum(s4, ex);
        if (ex < kk && kk <= ex + s4){
            int c = ex;
#pragma unroll
            for (int j = 0; j < 4; j++){
                c += (int)hist[b0 + j];
                if (c >= kk){ sB = b0 + j; break; }
            }
        }
    }
    __syncthreads();
    int B = sB;

    // single-pass unordered compaction; composite key restores canonical order
    for (int s = t; s < n; s += 1024){
        unsigned d = ~fordera(base[s]);
        if ((int)(d >> 20) <= B){
            unsigned pos = atomicAdd(&sCnt, 1u);
            if (pos < SELCAP)
                skey[pos] = ((unsigned long long)d << 16) | (unsigned long long)s;
        }
    }
    __syncthreads();
    unsigned cntAll = sCnt; if (cntAll > SELCAP) cntAll = SELCAP;
    for (int s = (int)cntAll + t; s < SELCAP; s += 1024) skey[s] = ~0ull;
    __syncthreads();

    unsigned long long keys[4];
#pragma unroll
    for (int j = 0; j < 4; j++) keys[j] = skey[t*4 + j];
    __syncthreads();
    SelSortT(*sortTS).Sort(keys, 0, 48);             // (desckey asc, anchor asc)

    // fused candidate build
    size_t sbase = (size_t)seg * SEGCAP;
    float lmax = 0.f;
#pragma unroll
    for (int j = 0; j < 4; j++){
        int pos = t*4 + j;
        if (pos < kk){
            unsigned long long key = keys[j];
            int s = (int)(key & 0xFFFFull);
            unsigned d = (unsigned)(key >> 16);
            unsigned f = ~d;                         // fordera bits
            unsigned ob = (f & 0x80000000u) ? (f & 0x7FFFFFFFu) : ~f;
            float o = __uint_as_float(ob);
            int gi = i*ATOT + loff_of(l) + s;
            float4 b = *(const float4*)(props + (size_t)gi*4);
            float x1 = fminf(fmaxf(b.x, 0.f), 512.f);
            float y1 = fminf(fmaxf(b.y, 0.f), 512.f);
            float x2 = fminf(fmaxf(b.z, 0.f), 512.f);
            float y2 = fminf(fmaxf(b.w, 0.f), 512.f);
            float sc = sigmoid_ref(o);
            float ws = __fsub_rn(x2, x1), hs = __fsub_rn(y2, y1);
            bool v = (ws >= 0.001f) && (hs >= 0.001f) && (sc >= 0.0f);
            g_cbox[sbase + pos]  = make_float4(x1, y1, x2, y2);
            g_score[sbase + pos] = sc;
            if (!v) atomicOr(&g_seginval[seg*32 + (pos >> 6)], 1ull << (pos & 63));
            lmax = fmaxf(lmax, fmaxf(fmaxf(x1, y1), fmaxf(x2, y2)));
        }
    }
    atomicMax(&sMax, __float_as_uint(lmax));         // coords >= 0: uint max == fp max
    __syncthreads();
    if (t == 0) g_segmax[seg] = sMax;
}

// IoU mask: overlap prescreen + exact division-free test; offsets computed on the fly.
__global__ void __launch_bounds__(256) k_iou(){
    int seg = blockIdx.y;
    int l = seg % 5, i = seg / 5;
    int m = segk_of(l);
    int wid  = threadIdx.x >> 5;
    int gw   = blockIdx.x*8 + wid;
    int lane = threadIdx.x & 31;
    int w = gw & 31;
    int rowBlk = gw >> 5;
    int row0 = rowBlk*128;
    if (row0 >= m) return;
    size_t base = (size_t)seg * SEGCAP;
    int j0 = w * 64;

    __shared__ float4 sB[8][64];
    __shared__ float  sAr[8][64];

    float off = __fmul_rn((float)l, img_mp1(i));

    int rows[4];
#pragma unroll
    for (int k = 0; k < 4; k++) rows[k] = row0 + k*32 + lane;

    unsigned long long bits[4] = {0,0,0,0}, amb[4] = {0,0,0,0};

    if (j0 + 63 > row0){
        int jend = min(j0 + 64, m);
#pragma unroll
        for (int s = 0; s < 2; s++){
            int jj = lane + s*32;
            if (j0 + jj < m){
                float4 c = g_cbox[base + j0 + jj];
                float4 ob = make_float4(__fadd_rn(c.x, off), __fadd_rn(c.y, off),
                                        __fadd_rn(c.z, off), __fadd_rn(c.w, off));
                sB[wid][jj]  = ob;
                sAr[wid][jj] = __fmul_rn(__fsub_rn(ob.z, ob.x), __fsub_rn(ob.w, ob.y));
            }
        }
        __syncwarp();

        float4 A[4]; float aA[4];
#pragma unroll
        for (int k = 0; k < 4; k++){
            float4 c = g_cbox[base + rows[k]];
            A[k] = make_float4(__fadd_rn(c.x, off), __fadd_rn(c.y, off),
                               __fadd_rn(c.z, off), __fadd_rn(c.w, off));
            aA[k] = __fmul_rn(__fsub_rn(A[k].z, A[k].x), __fsub_rn(A[k].w, A[k].y));
        }

        unsigned long long xm[4] = {0,0,0,0};
        for (int j = j0; j < jend; j++){
            float4 B = sB[wid][j - j0];
            unsigned long long bm = 1ull << (j - j0);
#pragma unroll
            for (int k = 0; k < 4; k++){
                float ltx = fmaxf(A[k].x, B.x), lty = fmaxf(A[k].y, B.y);
                float rbx = fminf(A[k].z, B.z), rby = fminf(A[k].w, B.w);
                if (rbx > ltx && rby > lty) xm[k] |= bm;
            }
        }
#pragma unroll
        for (int k = 0; k < 4; k++){
            int cnt = rows[k] - j0 + 1;
            unsigned long long lowm = (cnt <= 0) ? 0ull :
                                      (cnt >= 64) ? ~0ull : ((1ull << cnt) - 1ull);
            xm[k] &= ~lowm;
        }
#pragma unroll
        for (int k = 0; k < 4; k++){
            unsigned long long x = xm[k];
            while (x){
                int b = __ffsll((long long)x) - 1;
                x &= x - 1ull;
                float4 B = sB[wid][b];
                float aB = sAr[wid][b];
                float ltx = fmaxf(A[k].x, B.x), lty = fmaxf(A[k].y, B.y);
                float rbx = fminf(A[k].z, B.z), rby = fminf(A[k].w, B.w);
                float ww = fmaxf(__fsub_rn(rbx, ltx), 0.f);
                float hh = fmaxf(__fsub_rn(rby, lty), 0.f);
                float inter = __fmul_rn(ww, hh);
                float s = __fadd_rn(aA[k], aB);
                float u = __fsub_rn(s, inter);
                float t = __fmaf_rn(0.7f, u, -inter);
                float tau = __fmul_rn(u, 2.384185791015625e-7f);
                unsigned long long bm = 1ull << b;
                if (t < -tau)        bits[k] |= bm;
                if (fabsf(t) <= tau) amb[k]  |= bm;
            }
        }
    }
#pragma unroll
    for (int k = 0; k < 4; k++){
        g_mask[(base + rows[k])*32 + w] = bits[k];
        unsigned long long am = amb[k];
        while (am){
            int b = __ffsll((long long)am) - 1;
            am &= am - 1ull;
            unsigned slot = atomicAdd(&g_ambcnt, 1u);
            if (slot < AMB_CAP)
                g_amb[slot] = ((unsigned)seg << 22) | ((unsigned)rows[k] << 11)
                            | (unsigned)(j0 + b);
        }
    }
}

// Word-block serial sweep + fused compaction: emits per-seg ascending key list.
__global__ void __launch_bounds__(32, 1) k_sweep(){
    int seg = blockIdx.x, lane = threadIdx.x;
    int l = seg % 5, i = seg / 5, m = segk_of(l);
    int nblk = (m + 63) >> 6;
    size_t base = (size_t)seg * SEGCAP;
    float off = __fmul_rn((float)l, img_mp1(i));

    // resolve ambiguous pairs exactly (this segment only) before reading mask
    unsigned n = g_ambcnt; if (n > AMB_CAP) n = AMB_CAP;
    for (unsigned u = lane; u < n; u += 32){
        unsigned e = g_amb[u];
        if ((int)(e >> 22) != seg) continue;
        int row = (int)((e >> 11) & 0x7FFu), j = (int)(e & 0x7FFu);
        float4 ca = g_cbox[base + row];
        float4 A = make_float4(__fadd_rn(ca.x, off), __fadd_rn(ca.y, off),
                               __fadd_rn(ca.z, off), __fadd_rn(ca.w, off));
        float aA = __fmul_rn(__fsub_rn(A.z, A.x), __fsub_rn(A.w, A.y));
        float4 cb = g_cbox[base + j];
        float4 B = make_float4(__fadd_rn(cb.x, off), __fadd_rn(cb.y, off),
                               __fadd_rn(cb.z, off), __fadd_rn(cb.w, off));
        float aB = __fmul_rn(__fsub_rn(B.z, B.x), __fsub_rn(B.w, B.y));
        float ltx = fmaxf(A.x, B.x), lty = fmaxf(A.y, B.y);
        float rbx = fminf(A.z, B.z), rby = fminf(A.w, B.w);
        float ww = fmaxf(__fsub_rn(rbx, ltx), 0.f);
        float hh = fmaxf(__fsub_rn(rby, lty), 0.f);
        float inter = __fmul_rn(ww, hh);
        float uu = __fsub_rn(__fadd_rn(aA, aB), inter);
        float tt = __fmaf_rn(0.7f, uu, -inter);
        float tau = __fmul_rn(uu, 2.384185791015625e-7f);
        bool guess = (tt < -tau);
        bool ex = exact_pred(inter, uu);
        if (ex != guess)
            atomicXor(&g_mask[(base + row)*32 + (j >> 6)], 1ull << (j & 63));
    }
    __syncwarp();
    __threadfence();

    __shared__ __align__(16) unsigned long long smb[3][64*32];  // 3 x 16KB ring
    const char* gsrc = (const char*)&g_mask[base*32];

    auto issue_blk = [&](int W, int b){
        unsigned dst = (unsigned)__cvta_generic_to_shared(&smb[b][0]) + lane*16;
        const char* src = gsrc + (size_t)W*16384 + lane*16;
#pragma unroll
        for (int c = 0; c < 32; c++){
            asm volatile("cp.async.cg.shared.global [%0], [%1], 16;"
                         :: "r"(dst + c*512), "l"(src + c*512));
        }
        asm volatile("cp.async.commit_group;" ::: "memory");
    };

    unsigned long long removed = g_seginval[seg*32 + lane];

    issue_blk(0, 0);
    if (nblk > 1) issue_blk(1, 1);

    for (int W = 0; W < nblk; W++){
        if (W + 1 < nblk) asm volatile("cp.async.wait_group 1;" ::: "memory");
        else              asm volatile("cp.async.wait_group 0;" ::: "memory");
        __syncwarp();

        const unsigned long long* sb = smb[W % 3];
        unsigned long long col[64];
#pragma unroll
        for (int j = 0; j < 64; j++) col[j] = sb[j*32 + lane];

        if (W + 2 < nblk) issue_blk(W + 2, (W + 2) % 3);

        unsigned long long rm = removed;
#pragma unroll
        for (int j = 0; j < 64; j++)
            if (!((rm >> j) & 1ull)) rm |= col[j];
        unsigned long long kw = ~__shfl_sync(0xFFFFFFFFu, rm, W);   // alive bits

        if (kw){
#pragma unroll
            for (int j = 0; j < 64; j++)
                removed |= col[j] & (unsigned long long)(-(long long)((kw >> j) & 1ull));
        }
    }

    // fused compaction: per-lane keep bits -> warp scan -> ascending key list
    unsigned long long keepw = ~removed;             // padding/invalid already 0
    int cnt = __popcll(keepw);
    int inc = cnt;
#pragma unroll
    for (int o = 1; o < 32; o <<= 1){
        int v = __shfl_up_sync(0xFFFFFFFFu, inc, o);
        if (lane >= o) inc += v;
    }
    int ex = inc - cnt;
    int coff = coff_of(l);
    unsigned long long kw2 = keepw;
    int idx = ex;
    while (kw2){
        int b = __ffsll((long long)kw2) - 1;
        kw2 &= kw2 - 1ull;
        int r = lane*64 + b;
        unsigned dk = ~fordera(g_score[base + r]);
        g_ckeys[base + idx] = ((unsigned long long)dk << 13)
                            | (unsigned long long)(coff + r);
        idx++;
    }
    if (lane == 31) g_segcnt[seg] = (unsigned)inc;
}

// Block-wide merge-path merge of two ascending u64 lists (unique keys).
__device__ void block_merge(const unsigned long long* A, int na,
                            const unsigned long long* B, int nb,
                            unsigned long long* out){
    int total = na + nb;
    int per = (total + 1023) / 1024;
    int d = threadIdx.x * per;
    if (d < total){
        int lo = max(0, d - nb), hi = min(d, na);
        while (lo < hi){
            int mid = (lo + hi) >> 1;
            if (A[mid] <= B[d - 1 - mid]) lo = mid + 1; else hi = mid;
        }
        int ia = lo, ib = d - lo;
        int end = min(d + per, total);
        for (int s = d; s < end; s++){
            bool ta = (ib >= nb) || (ia < na && A[ia] <= B[ib]);
            out[s] = ta ? A[ia++] : B[ib++];
        }
    }
    __syncthreads();
}

// Per-image: load 5 compact sorted lists, 5-way merge, emit.
__global__ void __launch_bounds__(1024) k_out(float* __restrict__ out){
    int i = blockIdx.x, t = threadIdx.x;
    extern __shared__ unsigned long long sbuf[];
    unsigned long long* A  = sbuf;            // 7168: concat kept lists
    unsigned long long* Bf = sbuf + 7168;
    unsigned long long* Cf = sbuf + 14336;

    int off[6]; off[0] = 0;
    for (int l = 0; l < 5; l++)
        off[l+1] = off[l] + (int)g_segcnt[i*5 + l];
    int ntot = off[5];

    for (int l = 0; l < 5; l++){
        int seg = i*5 + l, c = off[l+1] - off[l];
        size_t base = (size_t)seg * SEGCAP;
        for (int s = t; s < c; s += 1024) A[off[l] + s] = g_ckeys[base + s];
    }
    __syncthreads();

    int n01 = off[2] - off[0], n23 = off[4] - off[2];
    block_merge(A + off[0], off[1]-off[0], A + off[1], off[2]-off[1], Cf);
    block_merge(A + off[2], off[3]-off[2], A + off[3], off[4]-off[3], Cf + n01);
    block_merge(Cf, n01, Cf + n01, n23, Bf);
    block_merge(Bf, off[4], A + off[4], ntot - off[4], Cf);

    float* ob = out + (size_t)i*POST*4;
    float* os = out + (size_t)NIMG*POST*4 + (size_t)i*POST;
    int T = min(ntot, POST);
    for (int s = t; s < POST; s += 1024){
        if (s < T){
            unsigned long long key = Cf[s];
            int p = (int)(key & 8191ull);
            int l = lvl_of_p(p), r = p - coff_of(l);
            int idx = (i*5 + l)*SEGCAP + r;
            *(float4*)(ob + s*4) = g_cbox[idx];
            os[s] = g_score[idx];
        } else {
            *(float4*)(ob + s*4) = make_float4(0.f, 0.f, 0.f, 0.f);
            os[s] = 0.f;
        }
    }
}

// ---------------- launch ----------------
extern "C" void kernel_launch(void* const* d_in, const int* in_sizes, int n_in,
                              void* d_out, int out_size){
    const float* props = (const float*)d_in[0];
    const float* obj   = (const float*)d_in[1];
    float* out = (float*)d_out;

    size_t dyn1 = 32768 + sizeof(SelSortT::TempStorage);
    size_t dyn2 = 3u*7168u*sizeof(unsigned long long);        // 168 KB merge buffers

    cudaFuncSetAttribute(k_sel2, cudaFuncAttributeMaxDynamicSharedMemorySize, (int)dyn1);
    cudaFuncSetAttribute(k_out,  cudaFuncAttributeMaxDynamicSharedMemorySize, (int)dyn2);

    k_sel2 <<<NSEG, 1024, dyn1>>>(obj, props);
    dim3 giou(64, NSEG);
    k_iou  <<<giou, 256>>>();
    k_sweep<<<NSEG, 32>>>();
    k_out  <<<NIMG, 1024, dyn2>>>(out);
}

// round 17
// speedup vs baseline: 1.0211x; 1.0211x over previous
#include <cuda_runtime.h>
#include <cub/cub.cuh>
#include <cstdint>

#define NIMG 8
#define ATOT 65472
#define KC 6960
#define NSEG 40
#define SEGCAP 2048
#define SELCAP 4096
#define POST 2000
#define AMB_CAP 65536
#define NBIN 4096

// ---------------- static device scratch (no runtime allocation) ----------------
__device__ float4             g_cbox[NSEG*SEGCAP];       // clipped boxes, (seg,rank)
__device__ float              g_score[NSEG*SEGCAP];
__device__ unsigned           g_segmax[NSEG];            // float bits of per-seg coord max
__device__ unsigned long long g_seginval[NSEG*32];
__device__ unsigned long long g_mask[(size_t)NSEG*SEGCAP*32];  // ~21 MB suppression bitmask
__device__ unsigned long long g_ckeys[NSEG*SEGCAP];     // per-seg compact kept keys (asc)
__device__ unsigned           g_segcnt[NSEG];
__device__ unsigned           g_ambcnt;
__device__ unsigned           g_amb[AMB_CAP];

typedef cub::BlockRadixSort<unsigned long long, 1024, 4> SelSortT;   // 4-bit passes (R15 proven)

// ---------------- helpers ----------------
__device__ __forceinline__ int lvl_of_p(int p){
    return (p<2000)?0:(p<4000)?1:(p<6000)?2:(p<6768)?3:4;
}
__device__ __forceinline__ int loff_of(int l){
    return (l==0)?0:(l==1)?49152:(l==2)?61440:(l==3)?64512:65280;
}
__device__ __forceinline__ int nlvl_of(int l){
    return (l==0)?49152:(l==1)?12288:(l==2)?3072:(l==3)?768:192;
}
__device__ __forceinline__ int coff_of(int l){
    return (l==0)?0:(l==1)?2000:(l==2)?4000:(l==3)?6000:6768;
}
__device__ __forceinline__ int segk_of(int l){
    return (l<3)?2000:(l==3)?768:192;
}
__device__ __forceinline__ unsigned fordera(float f){
    unsigned b = __float_as_uint(f);
    return (b & 0x80000000u) ? ~b : (b | 0x80000000u);
}
// image coordinate max from per-segment maxes (exact max, order-free)
__device__ __forceinline__ float img_mp1(int i){
    float mx =            __uint_as_float(g_segmax[i*5+0]);
    mx = fmaxf(mx, __uint_as_float(g_segmax[i*5+1]));
    mx = fmaxf(mx, __uint_as_float(g_segmax[i*5+2]));
    mx = fmaxf(mx, __uint_as_float(g_segmax[i*5+3]));
    mx = fmaxf(mx, __uint_as_float(g_segmax[i*5+4]));
    return __fadd_rn(mx, 1.0f);
}

// XLA logistic: 0.5 + 0.5*tanh(0.5x), tanh = EmitFastTanh rational (Eigen coeffs).
__device__ __forceinline__ float sigmoid_ref(float x){
    float t  = __fmul_rn(0.5f, x);
    float r;
    if (fabsf(t) < 0.0004f) {
        r = t;
    } else {
        float tc = fmaxf(-9.0f, fminf(9.0f, t));
        float s  = __fmul_rn(tc, tc);
        float p  = __fmaf_rn(s, -2.76076847742355e-16f, 2.00018790482477e-13f);
        p = __fmaf_rn(p, s, -8.60467152213735e-11f);
        p = __fmaf_rn(p, s,  5.12229709037114e-08f);
        p = __fmaf_rn(p, s,  1.48572235717979e-05f);
        p = __fmaf_rn(p, s,  6.37261928875436e-04f);
        p = __fmaf_rn(p, s,  4.89352455891786e-03f);
        p = __fmul_rn(p, tc);
        float q = __fmaf_rn(s, 1.19825839466702e-06f, 1.18534705686654e-04f);
        q = __fmaf_rn(q, s, 2.26843463243900e-03f);
        q = __fmaf_rn(q, s, 4.89352518554385e-03f);
        r = __fdiv_rn(p, q);
    }
    return __fmaf_rn(0.5f, r, 0.5f);
}

// Exact predicate: RN(a/u) > 0.7f  <=>  a/u >= m,  m = 0.7f + 2^-25 = 23488103*2^-25.
__device__ __forceinline__ bool exact_pred(float a, float u){
    if (!(a > 0.f) || !(u > 0.f)) return false;
    unsigned ia = __float_as_uint(a), iu = __float_as_uint(u);
    int d = (int)(ia >> 23) - (int)(iu >> 23);
    if (d > 0)  return true;
    if (d < -1) return false;
    unsigned long long Ma = (ia & 0x7FFFFFu) | 0x800000u;
    unsigned long long Mu = (iu & 0x7FFFFFu) | 0x800000u;
    return (Ma << (d + 25)) >= 23488103ull * Mu;
}

// ---------------- kernels ----------------
// Fused per-segment: histogram threshold select + atomic compaction (48-bit
// composite key canonicalizes order) + in-block sort + candidate build.
__global__ void __launch_bounds__(1024) k_sel2(const float* __restrict__ obj,
                                               const float* __restrict__ props){
    int seg = blockIdx.x, i = seg/5, l = seg%5;
    int n = nlvl_of(l), kk = segk_of(l);
    int t = threadIdx.x;
    extern __shared__ unsigned char dsm[];
    unsigned* hist = (unsigned*)dsm;                          // 16KB
    unsigned long long* skey = (unsigned long long*)dsm;      // 32KB (aliases hist)
    auto* sortTS = reinterpret_cast<SelSortT::TempStorage*>(dsm + 32768);
    typedef cub::BlockScan<int, 1024> BS;
    __shared__ typename BS::TempStorage ts;
    __shared__ int sB;
    __shared__ unsigned sCnt, sMax;

    if (seg == 0 && t == 0) g_ambcnt = 0u;
    if (t == 0){ sCnt = 0u; sMax = 0u; }
    if (t < 32){                                     // padding ranks start invalid
        int r0 = t*64;
        unsigned long long v = (kk <= r0) ? ~0ull :
                               (kk >= r0+64) ? 0ull : (~0ull << (kk - r0));
        g_seginval[seg*32 + t] = v;
    }
    for (int b = t; b < NBIN; b += 1024) hist[b] = 0u;
    __syncthreads();

    const float* base = obj + (size_t)i*ATOT + loff_of(l);
    for (int s = t; s < n; s += 1024){
        unsigned d = ~fordera(base[s]);
        atomicAdd(&hist[d >> 20], 1u);
    }
    __syncthreads();

    {   // threshold bucket: first bucket where cumulative >= kk
        int b0 = t*4, s4 = 0;
#pragma unroll
        for (int j = 0; j < 4; j++) s4 += (int)hist[b0 + j];
        int ex;
        BS(ts).ExclusiveSum(s4, ex);
        if (ex < kk && kk <= ex + s4){
            int c = ex;
#pragma unroll
            for (int j = 0; j < 4; j++){
                c += (int)hist[b0 + j];
                if (c >= kk){ sB = b0 + j; break; }
            }
        }
    }
    __syncthreads();
    int B = sB;

    // single-pass unordered compaction; composite key restores canonical order
    for (int s = t; s < n; s += 1024){
        unsigned d = ~fordera(base[s]);
        if ((int)(d >> 20) <= B){
            unsigned pos = atomicAdd(&sCnt, 1u);
            if (pos < SELCAP)
                skey[pos] = ((unsigned long long)d << 16) | (unsigned long long)s;
        }
    }
    __syncthreads();
    unsigned cntAll = sCnt; if (cntAll > SELCAP) cntAll = SELCAP;
    for (int s = (int)cntAll + t; s < SELCAP; s += 1024) skey[s] = ~0ull;
    __syncthreads();

    unsigned long long keys[4];
#pragma unroll
    for (int j = 0; j < 4; j++) keys[j] = skey[t*4 + j];
    __syncthreads();
    SelSortT(*sortTS).Sort(keys, 0, 48);             // (desckey asc, anchor asc)

    // fused candidate build
    size_t sbase = (size_t)seg * SEGCAP;
    float lmax = 0.f;
#pragma unroll
    for (int j = 0; j < 4; j++){
        int pos = t*4 + j;
        if (pos < kk){
            unsigned long long key = keys[j];
            int s = (int)(key & 0xFFFFull);
            unsigned d = (unsigned)(key >> 16);
            unsigned f = ~d;                         // fordera bits
            unsigned ob = (f & 0x80000000u) ? (f & 0x7FFFFFFFu) : ~f;
            float o = __uint_as_float(ob);
            int gi = i*ATOT + loff_of(l) + s;
            float4 b = *(const float4*)(props + (size_t)gi*4);
            float x1 = fminf(fmaxf(b.x, 0.f), 512.f);
            float y1 = fminf(fmaxf(b.y, 0.f), 512.f);
            float x2 = fminf(fmaxf(b.z, 0.f), 512.f);
            float y2 = fminf(fmaxf(b.w, 0.f), 512.f);
            float sc = sigmoid_ref(o);
            float ws = __fsub_rn(x2, x1), hs = __fsub_rn(y2, y1);
            bool v = (ws >= 0.001f) && (hs >= 0.001f) && (sc >= 0.0f);
            g_cbox[sbase + pos]  = make_float4(x1, y1, x2, y2);
            g_score[sbase + pos] = sc;
            if (!v) atomicOr(&g_seginval[seg*32 + (pos >> 6)], 1ull << (pos & 63));
            lmax = fmaxf(lmax, fmaxf(fmaxf(x1, y1), fmaxf(x2, y2)));
        }
    }
    atomicMax(&sMax, __float_as_uint(lmax));         // coords >= 0: uint max == fp max
    __syncthreads();
    if (t == 0) g_segmax[seg] = sMax;
}

// IoU mask: overlap prescreen + exact division-free test; offsets computed on the fly.
__global__ void __launch_bounds__(256) k_iou(){
    int seg = blockIdx.y;
    int l = seg % 5, i = seg / 5;
    int m = segk_of(l);
    int wid  = threadIdx.x >> 5;
    int gw   = blockIdx.x*8 + wid;
    int lane = threadIdx.x & 31;
    int w = gw & 31;
    int rowBlk = gw >> 5;
    int row0 = rowBlk*128;
    if (row0 >= m) return;
    size_t base = (size_t)seg * SEGCAP;
    int j0 = w * 64;

    __shared__ float4 sB[8][64];
    __shared__ float  sAr[8][64];

    float off = __fmul_rn((float)l, img_mp1(i));

    int rows[4];
#pragma unroll
    for (int k = 0; k < 4; k++) rows[k] = row0 + k*32 + lane;

    unsigned long long bits[4] = {0,0,0,0}, amb[4] = {0,0,0,0};

    if (j0 + 63 > row0){
        int jend = min(j0 + 64, m);
#pragma unroll
        for (int s = 0; s < 2; s++){
            int jj = lane + s*32;
            if (j0 + jj < m){
                float4 c = g_cbox[base + j0 + jj];
                float4 ob = make_float4(__fadd_rn(c.x, off), __fadd_rn(c.y, off),
                                        __fadd_rn(c.z, off), __fadd_rn(c.w, off));
                sB[wid][jj]  = ob;
                sAr[wid][jj] = __fmul_rn(__fsub_rn(ob.z, ob.x), __fsub_rn(ob.w, ob.y));
            }
        }
        __syncwarp();

        float4 A[4]; float aA[4];
#pragma unroll
        for (int k = 0; k < 4; k++){
            float4 c = g_cbox[base + rows[k]];
            A[k] = make_float4(__fadd_rn(c.x, off), __fadd_rn(c.y, off),
                               __fadd_rn(c.z, off), __fadd_rn(c.w, off));
            aA[k] = __fmul_rn(__fsub_rn(A[k].z, A[k].x), __fsub_rn(A[k].w, A[k].y));
        }

        unsigned long long xm[4] = {0,0,0,0};
        for (int j = j0; j < jend; j++){
            float4 B = sB[wid][j - j0];
            unsigned long long bm = 1ull << (j - j0);
#pragma unroll
            for (int k = 0; k < 4; k++){
                float ltx = fmaxf(A[k].x, B.x), lty = fmaxf(A[k].y, B.y);
                float rbx = fminf(A[k].z, B.z), rby = fminf(A[k].w, B.w);
                if (rbx > ltx && rby > lty) xm[k] |= bm;
            }
        }
#pragma unroll
        for (int k = 0; k < 4; k++){
            int cnt = rows[k] - j0 + 1;
            unsigned long long lowm = (cnt <= 0) ? 0ull :
                                      (cnt >= 64) ? ~0ull : ((1ull << cnt) - 1ull);
            xm[k] &= ~lowm;
        }
#pragma unroll
        for (int k = 0; k < 4; k++){
            unsigned long long x = xm[k];
            while (x){
                int b = __ffsll((long long)x) - 1;
                x &= x - 1ull;
                float4 B = sB[wid][b];
                float aB = sAr[wid][b];
                float ltx = fmaxf(A[k].x, B.x), lty = fmaxf(A[k].y, B.y);
                float rbx = fminf(A[k].z, B.z), rby = fminf(A[k].w, B.w);
                float ww = fmaxf(__fsub_rn(rbx, ltx), 0.f);
                float hh = fmaxf(__fsub_rn(rby, lty), 0.f);
                float inter = __fmul_rn(ww, hh);
                float s = __fadd_rn(aA[k], aB);
                float u = __fsub_rn(s, inter);
                float t = __fmaf_rn(0.7f, u, -inter);
                float tau = __fmul_rn(u, 2.384185791015625e-7f);
                unsigned long long bm = 1ull << b;
                if (t < -tau)        bits[k] |= bm;
                if (fabsf(t) <= tau) amb[k]  |= bm;
            }
        }
    }
#pragma unroll
    for (int k = 0; k < 4; k++){
        g_mask[(base + rows[k])*32 + w] = bits[k];
        unsigned long long am = amb[k];
        while (am){
            int b = __ffsll((long long)am) - 1;
            am &= am - 1ull;
            unsigned slot = atomicAdd(&g_ambcnt, 1u);
            if (slot < AMB_CAP)
                g_amb[slot] = ((unsigned)seg << 22) | ((unsigned)rows[k] << 11)
                            | (unsigned)(j0 + b);
        }
    }
}

// Word-block serial sweep + fused compaction: emits per-seg ascending key list.
__global__ void __launch_bounds__(32, 1) k_sweep(){
    int seg = blockIdx.x, lane = threadIdx.x;
    int l = seg % 5, i = seg / 5, m = segk_of(l);
    int nblk = (m + 63) >> 6;
    size_t base = (size_t)seg * SEGCAP;
    float off = __fmul_rn((float)l, img_mp1(i));

    // resolve ambiguous pairs exactly (this segment only) before reading mask
    unsigned n = g_ambcnt; if (n > AMB_CAP) n = AMB_CAP;
    for (unsigned u = lane; u < n; u += 32){
        unsigned e = g_amb[u];
        if ((int)(e >> 22) != seg) continue;
        int row = (int)((e >> 11) & 0x7FFu), j = (int)(e & 0x7FFu);
        float4 ca = g_cbox[base + row];
        float4 A = make_float4(__fadd_rn(ca.x, off), __fadd_rn(ca.y, off),
                               __fadd_rn(ca.z, off), __fadd_rn(ca.w, off));
        float aA = __fmul_rn(__fsub_rn(A.z, A.x), __fsub_rn(A.w, A.y));
        float4 cb = g_cbox[base + j];
        float4 B = make_float4(__fadd_rn(cb.x, off), __fadd_rn(cb.y, off),
                               __fadd_rn(cb.z, off), __fadd_rn(cb.w, off));
        float aB = __fmul_rn(__fsub_rn(B.z, B.x), __fsub_rn(B.w, B.y));
        float ltx = fmaxf(A.x, B.x), lty = fmaxf(A.y, B.y);
        float rbx = fminf(A.z, B.z), rby = fminf(A.w, B.w);
        float ww = fmaxf(__fsub_rn(rbx, ltx), 0.f);
        float hh = fmaxf(__fsub_rn(rby, lty), 0.f);
        float inter = __fmul_rn(ww, hh);
        float uu = __fsub_rn(__fadd_rn(aA, aB), inter);
        float tt = __fmaf_rn(0.7f, uu, -inter);
        float tau = __fmul_rn(uu, 2.384185791015625e-7f);
        bool guess = (tt < -tau);
        bool ex = exact_pred(inter, uu);
        if (ex != guess)
            atomicXor(&g_mask[(base + row)*32 + (j >> 6)], 1ull << (j & 63));
    }
    __syncwarp();
    __threadfence();

    __shared__ __align__(16) unsigned long long smb[3][64*32];  // 3 x 16KB ring
    const char* gsrc = (const char*)&g_mask[base*32];

    auto issue_blk = [&](int W, int b){
        unsigned dst = (unsigned)__cvta_generic_to_shared(&smb[b][0]) + lane*16;
        const char* src = gsrc + (size_t)W*16384 + lane*16;
#pragma unroll
        for (int c = 0; c < 32; c++){
            asm volatile("cp.async.cg.shared.global [%0], [%1], 16;"
                         :: "r"(dst + c*512), "l"(src + c*512));
        }
        asm volatile("cp.async.commit_group;" ::: "memory");
    };

    unsigned long long removed = g_seginval[seg*32 + lane];

    issue_blk(0, 0);
    if (nblk > 1) issue_blk(1, 1);

    for (int W = 0; W < nblk; W++){
        if (W + 1 < nblk) asm volatile("cp.async.wait_group 1;" ::: "memory");
        else              asm volatile("cp.async.wait_group 0;" ::: "memory");
        __syncwarp();

        const unsigned long long* sb = smb[W % 3];
        unsigned long long col[64];
#pragma unroll
        for (int j = 0; j < 64; j++) col[j] = sb[j*32 + lane];

        if (W + 2 < nblk) issue_blk(W + 2, (W + 2) % 3);

        unsigned long long rm = removed;
#pragma unroll
        for (int j = 0; j < 64; j++)
            if (!((rm >> j) & 1ull)) rm |= col[j];
        unsigned long long kw = ~__shfl_sync(0xFFFFFFFFu, rm, W);   // alive bits

        if (kw){
#pragma unroll
            for (int j = 0; j < 64; j++)
                removed |= col[j] & (unsigned long long)(-(long long)((kw >> j) & 1ull));
        }
    }

    // fused compaction: per-lane keep bits -> warp scan -> ascending key list
    unsigned long long keepw = ~removed;             // padding/invalid already 0
    int cnt = __popcll(keepw);
    int inc = cnt;
#pragma unroll
    for (int o = 1; o < 32; o <<= 1){
        int v = __shfl_up_sync(0xFFFFFFFFu, inc, o);
        if (lane >= o) inc += v;
    }
    int ex = inc - cnt;
    int coff = coff_of(l);
    unsigned long long kw2 = keepw;
    int idx = ex;
    while (kw2){
        int b = __ffsll((long long)kw2) - 1;
        kw2 &= kw2 - 1ull;
        int r = lane*64 + b;
        unsigned dk = ~fordera(__ldg(&g_score[base + r]));
        g_ckeys[base + idx] = ((unsigned long long)dk << 13)
                            | (unsigned long long)(coff + r);
        idx++;
    }
    if (lane == 31) g_segcnt[seg] = (unsigned)inc;
}

// Block-wide merge-path merge of two ascending u64 lists (unique keys).
__device__ void block_merge(const unsigned long long* A, int na,
                            const unsigned long long* B, int nb,
                            unsigned long long* out){
    int total = na + nb;
    int per = (total + 1023) / 1024;
    int d = threadIdx.x * per;
    if (d < total){
        int lo = max(0, d - nb), hi = min(d, na);
        while (lo < hi){
            int mid = (lo + hi) >> 1;
            if (A[mid] <= B[d - 1 - mid]) lo = mid + 1; else hi = mid;
        }
        int ia = lo, ib = d - lo;
        int end = min(d + per, total);
        for (int s = d; s < end; s++){
            bool ta = (ib >= nb) || (ia < na && A[ia] <= B[ib]);
            out[s] = ta ? A[ia++] : B[ib++];
        }
    }
    __syncthreads();
}

// Per-image: load 5 compact sorted lists, 5-way merge, emit.
__global__ void __launch_bounds__(1024) k_out(float* __restrict__ out){
    int i = blockIdx.x, t = threadIdx.x;
    extern __shared__ unsigned long long sbuf[];
    unsigned long long* A  = sbuf;            // 7168: concat kept lists
    unsigned long long* Bf = sbuf + 7168;
    unsigned long long* Cf = sbuf + 14336;

    int off[6]; off[0] = 0;
    for (int l = 0; l < 5; l++)
        off[l+1] = off[l] + (int)g_segcnt[i*5 + l];
    int ntot = off[5];

    for (int l = 0; l < 5; l++){
        int seg = i*5 + l, c = off[l+1] - off[l];
        size_t base = (size_t)seg * SEGCAP;
        for (int s = t; s < c; s += 1024) A[off[l] + s] = g_ckeys[base + s];
    }
    __syncthreads();

    int n01 = off[2] - off[0], n23 = off[4] - off[2];
    block_merge(A + off[0], off[1]-off[0], A + off[1], off[2]-off[1], Cf);
    block_merge(A + off[2], off[3]-off[2], A + off[3], off[4]-off[3], Cf + n01);
    block_merge(Cf, n01, Cf + n01, n23, Bf);
    block_merge(Bf, off[4], A + off[4], ntot - off[4], Cf);

    float* ob = out + (size_t)i*POST*4;
    float* os = out + (size_t)NIMG*POST*4 + (size_t)i*POST;
    int T = min(ntot, POST);
    for (int s = t; s < POST; s += 1024){
        if (s < T){
            unsigned long long key = Cf[s];
            int p = (int)(key & 8191ull);
            int l = lvl_of_p(p), r = p - coff_of(l);
            int idx = (i*5 + l)*SEGCAP + r;
            *(float4*)(ob + s*4) = g_cbox[idx];
            os[s] = g_score[idx];
        } else {
            *(float4*)(ob + s*4) = make_float4(0.f, 0.f, 0.f, 0.f);
            os[s] = 0.f;
        }
    }
}

// ---------------- launch ----------------
extern "C" void kernel_launch(void* const* d_in, const int* in_sizes, int n_in,
                              void* d_out, int out_size){
    const float* props = (const float*)d_in[0];
    const float* obj   = (const float*)d_in[1];
    float* out = (float*)d_out;

    size_t dyn1 = 32768 + sizeof(SelSortT::TempStorage);
    size_t dyn2 = 3u*7168u*sizeof(unsigned long long);        // 168 KB merge buffers

    cudaFuncSetAttribute(k_sel2, cudaFuncAttributeMaxDynamicSharedMemorySize, (int)dyn1);
    cudaFuncSetAttribute(k_out,  cudaFuncAttributeMaxDynamicSharedMemorySize, (int)dyn2);

    k_sel2 <<<NSEG, 1024, dyn1>>>(obj, props);
    dim3 giou(64, NSEG);
    k_iou  <<<giou, 256>>>();
    k_sweep<<<NSEG, 32>>>();
    k_out  <<<NIMG, 1024, dyn2>>>(out);
}